// round 15
// baseline (speedup 1.0000x reference)
#include <cuda_runtime.h>
#include <cuda_bf16.h>

// Problem constants (fixed by the reference setup_inputs)
#define BB 2
#define NN 8192
#define MM 32768
#define SS 4096
#define NQ (BB * SS)          // 8192 queries
#define NT (BB * MM)          // 65536 targets

// Spatial grid: 32^3 cells per batch over [-4.8, 4.8], h = 0.3
#define G 32
#define GLO (-4.8f)
#define GH 0.3f
#define GINVH 3.33333333f
#define CELLS_PER_B (G * G * G)       // 32768
#define NC (BB * CELLS_PER_B)         // 65536

// Single fused kernel: 148 blocks (one per SM, co-resident) x 1024 threads
#define NBLK 148
#define TPB 1024
#define NTHREADS (NBLK * TPB)
#define WPB (TPB / 32)                 // 32 warps per block

// Scan decomposition: 64 scan-blocks x 1024 cells (1 cell per thread)
#define SCB 64
#define CPB (NC / SCB)                 // 1024
#define CPB_SHIFT 10                   // cell >> 10 == scan-block id

#define FULL 0xFFFFFFFFu

// Device scratch (no allocations allowed).
// g_count: zero at load; histogram +1/point, scatter -1/point -> restored to
// zero after every launch. g_bsum: zero at load; +1/point in phase 1, zeroed
// in phase 3 after its last read -> restored every launch. No zeroing phase.
__device__ float4 g_target4[NT];     // (x, y, z, cell-id-as-int-bits)
__device__ float4 g_tsorted[NT];     // cell-sorted targets
__device__ float4 g_pred4[NQ];       // gathered query points
__device__ int    g_count[NC];
__device__ int    g_cellstart[NC + 1];
__device__ int    g_bsum[SCB];
__device__ int           g_bar_count;       // resets to 0 at every barrier
__device__ volatile int  g_bar_gen;         // monotonic across barriers/replays

__device__ __forceinline__ void grid_barrier() {
    __syncthreads();
    if (threadIdx.x == 0) {
        __threadfence();
        int gen = g_bar_gen;
        int arrived = atomicAdd(&g_bar_count, 1);
        if (arrived == NBLK - 1) {
            g_bar_count = 0;
            __threadfence();
            g_bar_gen = gen + 1;
        } else {
            while (g_bar_gen == gen) { }
        }
        __threadfence();
    }
    __syncthreads();
}

__device__ __forceinline__ int cell_coord(float v) {
    int c = (int)((v - GLO) * GINVH);
    return min(max(c, 0), G - 1);
}

// idx is int32 on device (JAX x64-disabled coerces int64 -> int32).
__global__ void __launch_bounds__(TPB) fused_chamfer_kernel(
    const float* __restrict__ target,
    const float* __restrict__ pred,
    const int* __restrict__ idx,
    float* __restrict__ out
) {
    __shared__ int   iw[WPB];
    __shared__ int   sh_boff;
    __shared__ int   sh_qcur;
    __shared__ float fw[WPB];

    const int tid = blockIdx.x * TPB + threadIdx.x;
    const int lane = threadIdx.x & 31;
    const int wid = threadIdx.x >> 5;

    // ---- Phase 1: histogram targets (+ per-scan-block totals) + gather ----
    if (tid < NT) {
        int i = tid;
        float x = target[3 * i + 0];
        float y = target[3 * i + 1];
        float z = target[3 * i + 2];
        int b = i / MM;
        int cell = b * CELLS_PER_B +
                   ((cell_coord(z) * G + cell_coord(y)) * G + cell_coord(x));
        g_target4[i] = make_float4(x, y, z, __int_as_float(cell));
        atomicAdd(&g_count[cell], 1);
        atomicAdd(&g_bsum[cell >> CPB_SHIFT], 1);   // scan-block total
    }
    if (tid < NQ) {
        int b = tid / SS;
        int s = tid % SS;
        int j = min(max(idx[s], 0), NN - 1);
        const float* p = pred + ((long long)b * NN + j) * 3;
        g_pred4[tid] = make_float4(p[0], p[1], p[2], 0.0f);
    }
    if (tid == 0) out[0] = 0.0f;
    grid_barrier();

    // ---- Phase 2: block prefix over g_bsum + local scan -> g_cellstart ----
    if (blockIdx.x < SCB) {
        if (wid == 0) {
            int a = (lane < blockIdx.x) ? g_bsum[lane] : 0;
            int b = (lane + 32 < blockIdx.x) ? g_bsum[lane + 32] : 0;
            int s = a + b;
#pragma unroll
            for (int o = 16; o > 0; o >>= 1) s += __shfl_down_sync(FULL, s, o);
            if (lane == 0) sh_boff = s;
        }
        int c = g_count[blockIdx.x * CPB + threadIdx.x];
        int incl = c;
#pragma unroll
        for (int o = 1; o < 32; o <<= 1) {
            int t = __shfl_up_sync(FULL, incl, o);
            if (lane >= o) incl += t;
        }
        if (lane == 31) iw[wid] = incl;
        __syncthreads();
        if (wid == 0) {
            int w = iw[lane];                  // WPB == 32: all lanes valid
#pragma unroll
            for (int o = 1; o < 32; o <<= 1) {
                int t = __shfl_up_sync(FULL, w, o);
                if (lane >= o) w += t;
            }
            iw[lane] = w;
        }
        __syncthreads();
        int pre = sh_boff + incl - c + (wid > 0 ? iw[wid - 1] : 0);
        g_cellstart[blockIdx.x * CPB + threadIdx.x] = pre;
    }
    if (tid == 0) g_cellstart[NC] = NT;
    grid_barrier();

    // ---- Phase 3: scatter (consumes g_count to 0); zero g_bsum for replay ----
    if (tid < NT) {
        float4 t = g_target4[tid];
        int cell = __float_as_int(t.w);
        int old = atomicAdd(&g_count[cell], -1);     // old in [1..count]
        g_tsorted[g_cellstart[cell] + old - 1] = t;
    }
    if (tid < SCB) g_bsum[tid] = 0;
    grid_barrier();

    // Reset the block-local steal cursor (after the barrier's syncthreads).
    if (threadIdx.x == 0) sh_qcur = 0;
    __syncthreads();

    // ---- Phase 4: warp-per-query NN ----
    // Block b statically owns queries q = b + t*NBLK (55-56 of them); warps
    // steal t from a SHARED-MEMORY cursor (no global-atomic serialization).
    // Fast path: nearest-corner 2x2x2 box, 8 bounds in one round trip, flat
    // 3-SEL loop. Escalation (rare): lane-per-row full-box rescan from r=1.
    const float INF = __int_as_float(0x7F800000);
    const int nq_b = (NQ - blockIdx.x + NBLK - 1) / NBLK;
    float acc = 0.0f;

    for (;;) {
        int t0;
        if (lane == 0) t0 = atomicAdd(&sh_qcur, 1);
        t0 = __shfl_sync(FULL, t0, 0);
        if (t0 >= nq_b) break;
        const int q = blockIdx.x + t0 * NBLK;

        float4 qp = g_pred4[q];
        const float qx = qp.x, qy = qp.y, qz = qp.z;
        const int cbase = (q / SS) * CELLS_PER_B;

        // Nearest grid corner -> 2x2x2 box [c0, c0+1] per dim
        int cx0 = (int)floorf((qx - GLO) * GINVH + 0.5f) - 1;
        int cy0 = (int)floorf((qy - GLO) * GINVH + 0.5f) - 1;
        int cz0 = (int)floorf((qz - GLO) * GINVH + 0.5f) - 1;
        cx0 = min(max(cx0, 0), G - 2);
        cy0 = min(max(cy0, 0), G - 2);
        cz0 = min(max(cz0, 0), G - 2);

        // Lanes 0-3: row starts; lanes 4-7: row ends. One round trip.
        int v = 0;
        if (lane < 8) {
            int i = lane & 3;
            int cz = cz0 + (i >> 1);
            int cy = cy0 + (i & 1);
            int rowbase = cbase + (cz * G + cy) * G;
            v = (lane < 4) ? g_cellstart[rowbase + cx0]
                           : g_cellstart[rowbase + cx0 + 2];
        }
        int S0 = __shfl_sync(FULL, v, 0), E0 = __shfl_sync(FULL, v, 4);
        int S1 = __shfl_sync(FULL, v, 1), E1 = __shfl_sync(FULL, v, 5);
        int S2 = __shfl_sync(FULL, v, 2), E2 = __shfl_sync(FULL, v, 6);
        int S3 = __shfl_sync(FULL, v, 3), E3 = __shfl_sync(FULL, v, 7);
        int P1 = (E0 - S0);
        int P2 = P1 + (E1 - S1);
        int P3 = P2 + (E2 - S2);
        int total = P3 + (E3 - S3);
        int D0 = S0;
        int D1 = S1 - P1;
        int D2 = S2 - P2;
        int D3 = S3 - P3;

        float lbest = INF;
#pragma unroll 4
        for (int t = lane; t < total; t += 32) {
            int d = D0;
            if (t >= P1) d = D1;
            if (t >= P2) d = D2;
            if (t >= P3) d = D3;
            float4 tp = g_tsorted[d + t];
            float ddx = qx - tp.x;
            float ddy = qy - tp.y;
            float ddz = qz - tp.z;
            float d2 = fmaf(ddx, ddx, fmaf(ddy, ddy, ddz * ddz));
            lbest = fminf(lbest, d2);
        }
        float wbest = lbest;
#pragma unroll
        for (int o = 16; o > 0; o >>= 1)
            wbest = fminf(wbest, __shfl_xor_sync(FULL, wbest, o));

        // Exact stop bound: distance to box faces (domain-edge faces open)
        float m = INF;
        if (cx0 > 0)     m = fminf(m, qx - (GLO + (float)cx0 * GH));
        if (cx0 + 2 < G) m = fminf(m, (GLO + (float)(cx0 + 2) * GH) - qx);
        if (cy0 > 0)     m = fminf(m, qy - (GLO + (float)cy0 * GH));
        if (cy0 + 2 < G) m = fminf(m, (GLO + (float)(cy0 + 2) * GH) - qy);
        if (cz0 > 0)     m = fminf(m, qz - (GLO + (float)cz0 * GH));
        if (cz0 + 2 < G) m = fminf(m, (GLO + (float)(cz0 + 2) * GH) - qz);
        m = fmaxf(m, 0.0f);

        if (!(wbest <= m * m)) {
            // ---- Escalation: full-box rescan from r=1, lane-per-row ----
            const int hx = cell_coord(qx);
            const int hy = cell_coord(qy);
            const int hz = cell_coord(qz);
            for (int r = 1; r < G; r++) {
                const int bx0 = max(hx - r, 0), bx1 = min(hx + r, G - 1);
                const int by0 = max(hy - r, 0), by1 = min(hy + r, G - 1);
                const int bz0 = max(hz - r, 0), bz1 = min(hz + r, G - 1);
                const int ny = by1 - by0 + 1;
                const int nrows = (bz1 - bz0 + 1) * ny;

                float lb = INF;
                for (int rb = 0; rb < nrows; rb += 32) {
                    int rho = rb + lane;
                    int s0 = 0, e0 = 0;
                    if (rho < nrows) {
                        int cz = bz0 + rho / ny;
                        int cy = by0 + rho % ny;
                        int rowbase = cbase + (cz * G + cy) * G;
                        s0 = g_cellstart[rowbase + bx0];
                        e0 = g_cellstart[rowbase + bx1 + 1];
                    }
                    // Each lane walks its own row: 32 independent chains.
                    for (int i = s0; i < e0; i++) {
                        float4 tp = g_tsorted[i];
                        float ddx = qx - tp.x;
                        float ddy = qy - tp.y;
                        float ddz = qz - tp.z;
                        lb = fminf(lb,
                            fmaf(ddx, ddx, fmaf(ddy, ddy, ddz * ddz)));
                    }
                }
                float wm = lb;
#pragma unroll
                for (int o = 16; o > 0; o >>= 1)
                    wm = fminf(wm, __shfl_xor_sync(FULL, wm, o));
                wbest = fminf(wbest, wm);

                float mm = INF;
                if (bx0 > 0)     mm = fminf(mm, qx - (GLO + (float)bx0 * GH));
                if (bx1 < G - 1) mm = fminf(mm, (GLO + (float)(bx1 + 1) * GH) - qx);
                if (by0 > 0)     mm = fminf(mm, qy - (GLO + (float)by0 * GH));
                if (by1 < G - 1) mm = fminf(mm, (GLO + (float)(by1 + 1) * GH) - qy);
                if (bz0 > 0)     mm = fminf(mm, qz - (GLO + (float)bz0 * GH));
                if (bz1 < G - 1) mm = fminf(mm, (GLO + (float)(bz1 + 1) * GH) - qz);
                mm = fmaxf(mm, 0.0f);
                if (wbest <= mm * mm) break;
                if (bx0 == 0 && by0 == 0 && bz0 == 0 &&
                    bx1 == G - 1 && by1 == G - 1 && bz1 == G - 1) break;
            }
        }
        if (lane == 0) acc += sqrtf(fmaxf(wbest, 0.0f));
    }

    // Block-level sum of per-warp accumulators, then one atomicAdd per block.
    if (lane == 0) fw[wid] = acc;
    __syncthreads();
    if (threadIdx.x == 0) {
        float s = 0.0f;
#pragma unroll
        for (int w = 0; w < WPB; w++) s += fw[w];
        atomicAdd(out, s * (1.0f / (float)NQ));
    }
}

extern "C" void kernel_launch(void* const* d_in, const int* in_sizes, int n_in,
                              void* d_out, int out_size) {
    const float* pred = (const float*)d_in[0];
    const float* target = (const float*)d_in[1];
    const int* idx = (const int*)d_in[2];
    float* out = (float*)d_out;

    fused_chamfer_kernel<<<NBLK, TPB>>>(target, pred, idx, out);
}